// round 8
// baseline (speedup 1.0000x reference)
#include <cuda_runtime.h>

typedef unsigned long long ull;

#define NB 512
#define NS 1024
#define NL 64
#define NC 66
#define LN2 0.6931471805599453f

static __device__ __forceinline__ ull fma2_(ull a, ull b, ull c) {
    ull d; asm("fma.rn.f32x2 %0, %1, %2, %3;" : "=l"(d) : "l"(a), "l"(b), "l"(c)); return d;
}
static __device__ __forceinline__ ull add2_(ull a, ull b) {
    ull d; asm("add.rn.f32x2 %0, %1, %2;" : "=l"(d) : "l"(a), "l"(b)); return d;
}
static __device__ __forceinline__ ull pack2_(float lo, float hi) {
    ull d; asm("mov.b64 %0, {%1, %2};" : "=l"(d) : "f"(lo), "f"(hi)); return d;
}
static __device__ __forceinline__ float2 unpack2_(ull v) {
    float lo, hi; asm("mov.b64 {%0, %1}, %2;" : "=f"(lo), "=f"(hi) : "l"(v)); return make_float2(lo, hi);
}

__global__ void zero_out_kernel(float* out) { out[0] = 0.0f; }

__global__ void __launch_bounds__(256, 1)
crf_fwd_kernel(const float* __restrict__ pred,
               const int*   __restrict__ ref,
               const int*   __restrict__ seq_len,
               const float* __restrict__ trans,
               float*       __restrict__ out)
{
    // 4 chains per CTA, each chain: 2 warps on different SMSPs
    __shared__ __align__(16) float qbuf[4][2][64];
    __shared__ float red[4][4];
    __shared__ int lmax_sh;

    const int wid = threadIdx.x >> 5;     // 0..7
    const int c   = wid >> 1;             // chain in CTA: 0..3
    const int h   = wid & 1;              // which half of the state vector
    const int l   = threadIdx.x & 31;
    const int b   = (blockIdx.x << 2) + c;
    const int j   = (h << 5) + l;         // my single state 0..63
    const int L   = seq_len[b];

    if (threadIdx.x == 0) lmax_sh = 0;
    __syncthreads();
    if (l == 0 && h == 0) atomicMax(&lmax_sh, L);

    // E column for state j, packed f32x2 over input-state pairs: 32 regs
    ull e2[32];
#pragma unroll
    for (int k = 0; k < 32; ++k)
        e2[k] = pack2_(__expf(trans[(2 * k) * NC + j]), __expf(trans[(2 * k + 1) * NC + j]));
    const float Te = __expf(trans[j * NC + 65]);

    const float* pb = pred + (size_t)b * NS * NL;
    const int last = L - 1;

    // init: q1 = exp(pred[0] + T[start])
    float q = __expf(pb[j] + trans[64 * NC + j]);
    qbuf[c][0][j] = q;

    float vthr = q * Te;          // per-thread terminal capture (covers L == 1)
    int ecap = 0, esum = 0;

    // pred pipeline (depth 3): at top of step t, w = exp(row[t-1] - 4)
    float r1 = pb[(size_t)min(1, last) * NL + j];
    float r2 = pb[(size_t)min(2, last) * NL + j];
    float w = __expf(r1 - 4.0f);
    r1 = r2;
    r2 = pb[(size_t)min(3, last) * NL + j];

    __syncthreads();
    const int Lmax = lmax_sh;

    for (int t = 2; t <= Lmax; ++t) {
        const float* rp = qbuf[c][t & 1];          // q_{t-1}
        float*       wp = qbuf[c][(t & 1) ^ 1];
        const ulonglong2* rp2 = (const ulonglong2*)rp;

        // d_j = sum_i q_{t-1}[i] * E[i][j] : 8 LDS.128 + 32 FFMA2 (4 accums, depth 8)
        ull a0 = 0, a1 = 0, a2 = 0, a3 = 0;
#pragma unroll
        for (int k = 0; k < 8; ++k) {
            ulonglong2 v0 = rp2[2 * k];
            ulonglong2 v1 = rp2[2 * k + 1];
            a0 = fma2_(v0.x, e2[4 * k + 0], a0);
            a1 = fma2_(v0.y, e2[4 * k + 1], a1);
            a2 = fma2_(v1.x, e2[4 * k + 2], a2);
            a3 = fma2_(v1.y, e2[4 * k + 3], a3);
        }
        float2 f = unpack2_(add2_(add2_(a0, a1), add2_(a2, a3)));
        float d = (f.x + f.y) * w;

        // renorm every 8 steps (exact power of 2, uniform across the chain)
        if ((t & 7) == 0) {
            float m = rp[0];
            int e = ((__float_as_int(m) >> 23) & 0xFF) - 127;
            e = max(-100, min(100, e));
            d *= __int_as_float((unsigned)(127 - e) << 23);
            esum += e;
        }

        // branchless per-chain terminal capture
        bool cap = (t == L);
        vthr = cap ? d * Te : vthr;
        ecap = cap ? esum   : ecap;

        wp[j] = d;

        // off-path: pipeline rotate + prefetch
        w = __expf(r1 - 4.0f);
        r1 = r2;
        r2 = pb[(size_t)min(t + 2, last) * NL + j];
        asm volatile("prefetch.global.L2 [%0];" :: "l"(pb + (size_t)min(t + 8, last) * NL + j));

        __syncthreads();
    }

    // ---- real path score: 64 threads of the chain stride time ----
    float rsum = 0.0f;
    const int* rb = ref + (size_t)b * NS;
    for (int s = j; s < L; s += 64) {
        int r = rb[s];
        int p = (s == 0) ? 64 : rb[s - 1];
        rsum += pb[(size_t)s * NL + r] + trans[p * NC + r];
    }
    if (j == 0) rsum += trans[rb[L - 1] * NC + 65];

    // ---- reduce per warp, combine the chain's two warps ----
#pragma unroll
    for (int o = 16; o; o >>= 1) {
        vthr += __shfl_xor_sync(0xFFFFFFFFu, vthr, o);
        rsum += __shfl_xor_sync(0xFFFFFFFFu, rsum, o);
    }
    if (l == 0) {
        red[c][h * 2 + 0] = vthr;
        red[c][h * 2 + 1] = rsum;
    }
    __syncthreads();
    if (j == 0) {
        float s  = red[c][0] + red[c][2];
        float rs = red[c][1] + red[c][3];
        float contrib = 4.0f * (float)(L - 1) + LN2 * (float)ecap + __logf(s) - rs;
        atomicAdd(out, contrib);
    }
}

extern "C" void kernel_launch(void* const* d_in, const int* in_sizes, int n_in,
                              void* d_out, int out_size)
{
    const float* pred  = (const float*)d_in[0];
    const int*   refp  = (const int*)d_in[1];
    const int*   seq   = (const int*)d_in[2];
    const float* trans = (const float*)d_in[3];
    float* outp = (float*)d_out;

    zero_out_kernel<<<1, 1>>>(outp);
    crf_fwd_kernel<<<NB / 4, 256>>>(pred, refp, seq, trans, outp);
}

// round 9
// speedup vs baseline: 1.6432x; 1.6432x over previous
#include <cuda_runtime.h>

typedef unsigned long long ull;

#define NB 512
#define NS 1024
#define NL 64
#define NC 66
#define LN2 0.6931471805599453f

static __device__ __forceinline__ ull fma2_(ull a, ull b, ull c) {
    ull d; asm("fma.rn.f32x2 %0, %1, %2, %3;" : "=l"(d) : "l"(a), "l"(b), "l"(c)); return d;
}
static __device__ __forceinline__ ull add2_(ull a, ull b) {
    ull d; asm("add.rn.f32x2 %0, %1, %2;" : "=l"(d) : "l"(a), "l"(b)); return d;
}
static __device__ __forceinline__ ull pack2_(float lo, float hi) {
    ull d; asm("mov.b64 %0, {%1, %2};" : "=l"(d) : "f"(lo), "f"(hi)); return d;
}
static __device__ __forceinline__ float2 unpack2_(ull v) {
    float lo, hi; asm("mov.b64 {%0, %1}, %2;" : "=f"(lo), "=f"(hi) : "l"(v)); return make_float2(lo, hi);
}

__global__ void zero_out_kernel(float* out) { out[0] = 0.0f; }

__global__ void __launch_bounds__(128, 1)
crf_fwd_kernel(const float* __restrict__ pred,
               const int*   __restrict__ ref,
               const int*   __restrict__ seq_len,
               const float* __restrict__ trans,
               float*       __restrict__ out)
{
    __shared__ __align__(16) float qbuf[4][2][64];

    const int w = threadIdx.x >> 5;        // warp = chain
    const int l = threadIdx.x & 31;
    const int b = (blockIdx.x << 2) + w;
    const int j0 = 2 * l, j1 = 2 * l + 1;
    const int L = seq_len[b];

    // E columns for states j0, j1: 128 regs
    ull e0[32], e1[32];
#pragma unroll
    for (int k = 0; k < 32; ++k) {
        e0[k] = pack2_(__expf(trans[(2 * k) * NC + j0]), __expf(trans[(2 * k + 1) * NC + j0]));
        e1[k] = pack2_(__expf(trans[(2 * k) * NC + j1]), __expf(trans[(2 * k + 1) * NC + j1]));
    }
    const float Te0 = __expf(trans[j0 * NC + 65]);
    const float Te1 = __expf(trans[j1 * NC + 65]);

    const float* pb = pred + (size_t)b * NS * NL;
    const float2* p2 = (const float2*)pb;
    const int last = L - 1;

    // init: q1 = exp(pred[0] + T[start]); cur regs carry the live q pair
    float cur0 = __expf(pb[j0] + trans[64 * NC + j0]);
    float cur1 = __expf(pb[j1] + trans[64 * NC + j1]);
    int esum = 0;

    float* buf0 = qbuf[w][0];
    float* buf1 = qbuf[w][1];
    ((float2*)buf0)[l] = make_float2(cur0, cur1);   // q_1 in buf0

    // pred pipeline (depth 3): at top of step t, w0/w1 = exp(row[t-1]-4)
    float2 r1 = p2[(size_t)min(1, last) * 32 + l];
    float2 r2 = p2[(size_t)min(2, last) * 32 + l];
    float w0 = __expf(r1.x - 4.0f);
    float w1 = __expf(r1.y - 4.0f);
    r1 = r2;
    r2 = p2[(size_t)min(3, last) * 32 + l];

    __syncwarp(0xFFFFFFFFu);

    for (int t = 2; t <= L; ++t) {
        const float* rp = (t & 1) ? buf1 : buf0;
        float*       wp = (t & 1) ? buf0 : buf1;
        const ulonglong2* rp2 = (const ulonglong2*)rp;

        // dual matvec: 16 LDS.128 + 64 FFMA2, 8 accumulators
        ull a0 = 0, a1 = 0, a2 = 0, a3 = 0;
        ull c0 = 0, c1 = 0, c2 = 0, c3 = 0;
#pragma unroll
        for (int k = 0; k < 8; ++k) {
            ulonglong2 v0 = rp2[2 * k];
            ulonglong2 v1 = rp2[2 * k + 1];
            a0 = fma2_(v0.x, e0[4 * k + 0], a0);
            c0 = fma2_(v0.x, e1[4 * k + 0], c0);
            a1 = fma2_(v0.y, e0[4 * k + 1], a1);
            c1 = fma2_(v0.y, e1[4 * k + 1], c1);
            a2 = fma2_(v1.x, e0[4 * k + 2], a2);
            c2 = fma2_(v1.x, e1[4 * k + 2], c2);
            a3 = fma2_(v1.y, e0[4 * k + 3], a3);
            c3 = fma2_(v1.y, e1[4 * k + 3], c3);
        }
        float2 fa = unpack2_(add2_(add2_(a0, a1), add2_(a2, a3)));
        float2 fc = unpack2_(add2_(add2_(c0, c1), add2_(c2, c3)));
        float d0 = (fa.x + fa.y) * w0;
        float d1 = (fc.x + fc.y) * w1;

        // renorm every 8 steps (exact power of 2, warp-uniform)
        if ((t & 7) == 0) {
            float m = rp[0];
            int e = ((__float_as_int(m) >> 23) & 0xFF) - 127;
            e = max(-100, min(100, e));
            float f = __int_as_float((unsigned)(127 - e) << 23);
            d0 *= f; d1 *= f;
            esum += e;
        }

        cur0 = d0; cur1 = d1;
        ((float2*)wp)[l] = make_float2(d0, d1);

        // pipeline rotate (off the recurrence)
        w0 = __expf(r1.x - 4.0f);
        w1 = __expf(r1.y - 4.0f);
        r1 = r2;
        r2 = p2[(size_t)min(t + 2, last) * 32 + l];

        __syncwarp(0xFFFFFFFFu);
    }

    // terminal capture after the loop (cur = q_L; covers L==1 via init)
    float v = cur0 * Te0 + cur1 * Te1;

    // ---- real path score (lane-strided gather) ----
    float rsum = 0.0f;
    const int* rb = ref + (size_t)b * NS;
    for (int s = l; s < L; s += 32) {
        int r = rb[s];
        int p = (s == 0) ? 64 : rb[s - 1];
        rsum += pb[(size_t)s * NL + r] + trans[p * NC + r];
    }
    if (l == 0) rsum += trans[rb[L - 1] * NC + 65];

    // ---- in-warp reduction; one atomic per chain ----
#pragma unroll
    for (int o = 16; o; o >>= 1) {
        v    += __shfl_xor_sync(0xFFFFFFFFu, v, o);
        rsum += __shfl_xor_sync(0xFFFFFFFFu, rsum, o);
    }
    if (l == 0) {
        float contrib = 4.0f * (float)(L - 1) + LN2 * (float)esum + __logf(v) - rsum;
        atomicAdd(out, contrib);
    }
}

extern "C" void kernel_launch(void* const* d_in, const int* in_sizes, int n_in,
                              void* d_out, int out_size)
{
    const float* pred  = (const float*)d_in[0];
    const int*   refp  = (const int*)d_in[1];
    const int*   seq   = (const int*)d_in[2];
    const float* trans = (const float*)d_in[3];
    float* outp = (float*)d_out;

    zero_out_kernel<<<1, 1>>>(outp);
    crf_fwd_kernel<<<NB / 4, 128>>>(pred, refp, seq, trans, outp);
}